// round 10
// baseline (speedup 1.0000x reference)
#include <cuda_runtime.h>

// MakeCutouts: 32 cutouts of x[8,3,512,512] fp32, adaptive-avg-pool (torch
// bins) to 224x224. Output [256, 3, 224, 224] fp32.
//
// Block = (cut, plane, 8-row y-group), 256 threads, smem 16.5KB, 1 barrier.
//   Phase 1: half 0 (threads 0-127) bins 0-3, half 1 bins 4-7; consecutive
//            bins per half, <=1-row overlap carried in registers; float4
//            loads aligned-down from ox.
//   Phase 2: 224 threads x 8 rows, nx (<=MAXTAP) shared taps each.
// MAXTAP=3 when sz<=448 (bin width < r+2 <= 4 -> <=3); else 4. Uniform branch.
// All indexing 32-bit (max offsets ~38.5M).

#define OUTS   224
#define BATCH  8
#define CHAN   3
#define HW     512
#define CUTN   32
#define NPLANE (BATCH * CHAN)   // 24
#define YG     8
#define NYG    (OUTS / YG)      // 28
#define BPH    4
#define CSTRIDE 516

__device__ __forceinline__ float inv_small(int n) {
    return n == 1 ? 1.0f : (n == 2 ? 0.5f : (n == 3 ? (1.0f / 3.0f) : 0.25f));
}
__device__ __forceinline__ void f4add(float4& a, const float4 b) {
    a.x += b.x; a.y += b.y; a.z += b.z; a.w += b.w;
}

template<int MAXTAP>
__device__ __forceinline__ void body(
    float (*buf)[CSTRIDE], float* invy_sh,
    const float* __restrict__ pbase, float* __restrict__ out,
    int sz, int shift, int span, int y0, int tid, int obase)
{
    const int lane = tid & 127;
    const int half = tid >> 7;
    const int rem  = span - lane * 4;
    const int col4 = lane * 4;
    const int yb   = y0 + half * BPH;

    if (tid < YG) {
        const int yy = y0 + tid;
        const int ny = ((yy + 1) * sz + (OUTS - 1)) / OUTS - (yy * sz) / OUTS;
        invy_sh[tid] = inv_small(ny);
    }

    // ---- Phase 1 ----
    if (rem >= 4) {
        float4 last; int pe = -1000;
        #pragma unroll
        for (int j = 0; j < BPH; j++) {
            const int y  = yb + j;
            const int sy = (y * sz) / OUTS;
            const int ey = ((y + 1) * sz + (OUTS - 1)) / OUTS;
            const int ny = ey - sy;
            const float* rp = pbase + sy * HW + col4;

            float4 acc, l;
            if (sy == pe - 1) { acc = last; l = last; }
            else              { l = __ldg((const float4*)rp); acc = l; }
            if (ny > 1) { l = __ldg((const float4*)(rp + HW));     f4add(acc, l); }
            if (ny > 2) { l = __ldg((const float4*)(rp + 2 * HW)); f4add(acc, l); }
            if (MAXTAP > 3 && ny > 3) {
                l = __ldg((const float4*)(rp + 3 * HW)); f4add(acc, l);
            }
            *(float4*)&buf[half * BPH + j][col4] = acc;
            last = l; pe = ey;
        }
    } else if (rem > 0) {
        #pragma unroll
        for (int j = 0; j < BPH; j++) {
            const int y  = yb + j;
            const int sy = (y * sz) / OUTS;
            const int ny = ((y + 1) * sz + (OUTS - 1)) / OUTS - sy;
            const float* rp = pbase + sy * HW + col4;
            #pragma unroll
            for (int k = 0; k < 3; k++) {
                if (k < rem) {
                    float s = __ldg(rp + k);
                    if (ny > 1) s += __ldg(rp + k + HW);
                    if (ny > 2) s += __ldg(rp + k + 2 * HW);
                    if (MAXTAP > 3 && ny > 3) s += __ldg(rp + k + 3 * HW);
                    buf[half * BPH + j][col4 + k] = s;
                }
            }
        }
    }
    if (MAXTAP > 3 && span > 512 && tid == 126) {   // cols 512..514 (rare)
        #pragma unroll 1
        for (int j = 0; j < YG; j++) {
            const int y  = y0 + j;
            const int sy = (y * sz) / OUTS;
            const int ny = ((y + 1) * sz + (OUTS - 1)) / OUTS - sy;
            for (int c = 512; c < span && c < 515; c++) {
                const float* q = pbase + sy * HW + c;
                float s = __ldg(q);
                if (ny > 1) s += __ldg(q + HW);
                if (ny > 2) s += __ldg(q + 2 * HW);
                if (ny > 3) s += __ldg(q + 3 * HW);
                buf[j][c] = s;
            }
        }
    }

    __syncthreads();

    // ---- Phase 2 ----
    if (tid < OUTS) {
        const int sx = (tid * sz) / OUTS;
        const int ex = ((tid + 1) * sz + (OUTS - 1)) / OUTS;
        const int nx = ex - sx;
        const float invx = inv_small(nx);
        const int off = shift + sx;

        int oidx = obase + tid;
        #pragma unroll
        for (int i = 0; i < YG; i++) {
            const float* p = &buf[i][off];
            float s = p[0];
            if (nx > 1) s += p[1];
            if (nx > 2) s += p[2];
            if (MAXTAP > 3 && nx > 3) s += p[3];
            out[oidx] = s * (invx * invy_sh[i]);
            oidx += OUTS;
        }
    }
}

__global__ __launch_bounds__(256)
void makecutouts_v9(const float* __restrict__ x,
                    const int* __restrict__ sizes,
                    const int* __restrict__ offy,
                    const int* __restrict__ offx,
                    float* __restrict__ out)
{
    __shared__ float buf[YG][CSTRIDE];   // 16,512 B
    __shared__ float invy_sh[YG];

    const int tid = threadIdx.x;
    int bid = blockIdx.x;
    const int yg    = bid % NYG;  bid /= NYG;
    const int plane = bid % NPLANE;
    const int cut   = bid / NPLANE;

    const int sz = __ldg(sizes + cut);
    const int oy = __ldg(offy + cut);
    const int ox = __ldg(offx + cut);

    const int ox_al = ox & ~3;
    const int shift = ox - ox_al;        // 0..3
    const int span  = shift + sz;        // <= 515
    const int y0 = yg * YG;

    const float* pbase = x + plane * (HW * HW) + oy * HW + ox_al;
    const int obase = ((cut * NPLANE + plane) * OUTS + y0) * OUTS;

    if (sz <= 448)
        body<3>(buf, invy_sh, pbase, out, sz, shift, span, y0, tid, obase);
    else
        body<4>(buf, invy_sh, pbase, out, sz, shift, span, y0, tid, obase);
}

extern "C" void kernel_launch(void* const* d_in, const int* in_sizes, int n_in,
                              void* d_out, int out_size)
{
    const float* x     = (const float*)d_in[0];
    const int*   sizes = (const int*)d_in[1];
    const int*   oy    = (const int*)d_in[2];
    const int*   ox    = (const int*)d_in[3];
    float* out = (float*)d_out;

    const int blocks = CUTN * NPLANE * NYG;   // 21504
    makecutouts_v9<<<blocks, 256>>>(x, sizes, oy, ox, out);
}

// round 11
// speedup vs baseline: 1.5041x; 1.5041x over previous
#include <cuda_runtime.h>

// MakeCutouts: 32 cutouts of x[8,3,512,512] fp32, adaptive-avg-pool (torch
// bins) to 224x224. Output [256, 3, 224, 224] fp32.
//
// v7 structure exactly (1 barrier, direct __shared__ refs, float4 phase 1
// with register-carried <=1-row bin overlap, 224-thread phase 2), plus a
// uniform sz<=448 branch that statically prunes the 4th tap (r<=2 -> bins
// span <=3 input pixels). No helper functions: phase code duplicated inline
// so shared-memory accesses stay direct STS/LDS.

#define OUTS   224
#define BATCH  8
#define CHAN   3
#define HW     512
#define CUTN   32
#define NPLANE (BATCH * CHAN)   // 24
#define YG     8                // output rows per block
#define NYG    (OUTS / YG)      // 28
#define BPH    4                // bins per half
#define CSTRIDE 516

__device__ __forceinline__ float inv_small(int n) {
    return n == 1 ? 1.0f : (n == 2 ? 0.5f : (n == 3 ? (1.0f / 3.0f) : 0.25f));
}

__device__ __forceinline__ void f4add(float4& a, const float4 b) {
    a.x += b.x; a.y += b.y; a.z += b.z; a.w += b.w;
}

__global__ __launch_bounds__(256)
void makecutouts_v10(const float* __restrict__ x,
                     const int* __restrict__ sizes,
                     const int* __restrict__ offy,
                     const int* __restrict__ offx,
                     float* __restrict__ out)
{
    __shared__ float buf[YG][CSTRIDE];   // 16,512 B
    __shared__ float invy_sh[YG];

    const int tid = threadIdx.x;
    int bid = blockIdx.x;
    const int yg    = bid % NYG;  bid /= NYG;
    const int plane = bid % NPLANE;
    const int cut   = bid / NPLANE;

    const int sz = __ldg(sizes + cut);
    const int oy = __ldg(offy + cut);
    const int ox = __ldg(offx + cut);

    const int ox_al = ox & ~3;
    const int shift = ox - ox_al;        // 0..3
    const int span  = shift + sz;        // <= 515
    const int y0 = yg * YG;

    if (tid < YG) {
        const int yy = y0 + tid;
        const int ny = ((yy + 1) * sz + (OUTS - 1)) / OUTS - (yy * sz) / OUTS;
        invy_sh[tid] = inv_small(ny);
    }

    const float* pbase = x + (long long)plane * (HW * HW) + ox_al
                           + (long long)oy * HW;

    const int lane = tid & 127;
    const int half = tid >> 7;
    const int rem  = span - lane * 4;
    const int col4 = lane * 4;
    const int yb   = y0 + half * BPH;

    const bool small = (sz <= 448);      // uniform per block

    // ================= Phase 1 =================
    if (small) {
        // ---- <=3 taps ----
        if (rem >= 4) {
            float4 last; int pe = -1000;
            #pragma unroll
            for (int j = 0; j < BPH; j++) {
                const int y  = yb + j;
                const int sy = (y * sz) / OUTS;
                const int ey = ((y + 1) * sz + (OUTS - 1)) / OUTS;
                const int ny = ey - sy;           // 1..3
                const float* rp = pbase + (long long)sy * HW + col4;

                float4 acc, l;
                if (sy == pe - 1) { acc = last; l = last; }
                else              { l = __ldg((const float4*)rp); acc = l; }
                if (ny > 1) { l = __ldg((const float4*)(rp + HW));     f4add(acc, l); }
                if (ny > 2) { l = __ldg((const float4*)(rp + 2 * HW)); f4add(acc, l); }
                *(float4*)&buf[half * BPH + j][col4] = acc;
                last = l; pe = ey;
            }
        } else if (rem > 0) {
            #pragma unroll
            for (int j = 0; j < BPH; j++) {
                const int y  = yb + j;
                const int sy = (y * sz) / OUTS;
                const int ny = ((y + 1) * sz + (OUTS - 1)) / OUTS - sy;
                const float* rp = pbase + (long long)sy * HW + col4;
                #pragma unroll
                for (int k = 0; k < 3; k++) {
                    if (k < rem) {
                        float s = __ldg(rp + k);
                        if (ny > 1) s += __ldg(rp + k + HW);
                        if (ny > 2) s += __ldg(rp + k + 2 * HW);
                        buf[half * BPH + j][col4 + k] = s;
                    }
                }
            }
        }
        // span <= 452 here: no tail-column handling needed
    } else {
        // ---- <=4 taps ----
        if (rem >= 4) {
            float4 last; int pe = -1000;
            #pragma unroll
            for (int j = 0; j < BPH; j++) {
                const int y  = yb + j;
                const int sy = (y * sz) / OUTS;
                const int ey = ((y + 1) * sz + (OUTS - 1)) / OUTS;
                const int ny = ey - sy;           // 1..4
                const float* rp = pbase + (long long)sy * HW + col4;

                float4 acc, l;
                if (sy == pe - 1) { acc = last; l = last; }
                else              { l = __ldg((const float4*)rp); acc = l; }
                if (ny > 1) { l = __ldg((const float4*)(rp + HW));     f4add(acc, l); }
                if (ny > 2) { l = __ldg((const float4*)(rp + 2 * HW)); f4add(acc, l); }
                if (ny > 3) { l = __ldg((const float4*)(rp + 3 * HW)); f4add(acc, l); }
                *(float4*)&buf[half * BPH + j][col4] = acc;
                last = l; pe = ey;
            }
        } else if (rem > 0) {
            #pragma unroll
            for (int j = 0; j < BPH; j++) {
                const int y  = yb + j;
                const int sy = (y * sz) / OUTS;
                const int ny = ((y + 1) * sz + (OUTS - 1)) / OUTS - sy;
                const float* rp = pbase + (long long)sy * HW + col4;
                #pragma unroll
                for (int k = 0; k < 3; k++) {
                    if (k < rem) {
                        float s = __ldg(rp + k);
                        if (ny > 1) s += __ldg(rp + k + HW);
                        if (ny > 2) s += __ldg(rp + k + 2 * HW);
                        if (ny > 3) s += __ldg(rp + k + 3 * HW);
                        buf[half * BPH + j][col4 + k] = s;
                    }
                }
            }
        }
        // columns 512..514 (only when span > 512): thread 126 handles
        if (span > 512 && tid == 126) {
            #pragma unroll 1
            for (int j = 0; j < YG; j++) {
                const int y  = y0 + j;
                const int sy = (y * sz) / OUTS;
                const int ny = ((y + 1) * sz + (OUTS - 1)) / OUTS - sy;
                #pragma unroll
                for (int c = 512; c < 515; c++) {
                    if (c < span) {
                        const float* q = pbase + (long long)sy * HW + c;
                        float s = __ldg(q);
                        if (ny > 1) s += __ldg(q + HW);
                        if (ny > 2) s += __ldg(q + 2 * HW);
                        if (ny > 3) s += __ldg(q + 3 * HW);
                        buf[j][c] = s;
                    }
                }
            }
        }
    }

    __syncthreads();

    // ================= Phase 2 =================
    if (tid < OUTS) {
        const int sx = (tid * sz) / OUTS;
        const int ex = ((tid + 1) * sz + (OUTS - 1)) / OUTS;
        const int nx = ex - sx;              // 1..4 (<=3 when small)
        const float invx = inv_small(nx);
        const int off = shift + sx;

        long long oidx =
            ((long long)(cut * NPLANE + plane) * OUTS + y0) * OUTS + tid;

        if (small) {
            #pragma unroll
            for (int i = 0; i < YG; i++) {
                const float* p = &buf[i][off];
                float s = p[0];
                if (nx > 1) s += p[1];
                if (nx > 2) s += p[2];
                out[oidx] = s * (invx * invy_sh[i]);
                oidx += OUTS;
            }
        } else {
            #pragma unroll
            for (int i = 0; i < YG; i++) {
                const float* p = &buf[i][off];
                float s = p[0];
                if (nx > 1) s += p[1];
                if (nx > 2) s += p[2];
                if (nx > 3) s += p[3];
                out[oidx] = s * (invx * invy_sh[i]);
                oidx += OUTS;
            }
        }
    }
}

extern "C" void kernel_launch(void* const* d_in, const int* in_sizes, int n_in,
                              void* d_out, int out_size)
{
    const float* x     = (const float*)d_in[0];
    const int*   sizes = (const int*)d_in[1];
    const int*   oy    = (const int*)d_in[2];
    const int*   ox    = (const int*)d_in[3];
    float* out = (float*)d_out;

    const int blocks = CUTN * NPLANE * NYG;   // 21504
    makecutouts_v10<<<blocks, 256>>>(x, sizes, oy, ox, out);
}

// round 12
// speedup vs baseline: 1.5057x; 1.0011x over previous
#include <cuda_runtime.h>

// MakeCutouts: 32 cutouts of x[8,3,512,512] fp32, adaptive-avg-pool (torch
// bins) to 224x224. Output [256, 3, 224, 224] fp32.
//
// v10 structure (1 barrier, direct __shared__ refs, float4 phase 1 with
// register-carried <=1-row bin overlap, uniform sz<=448 MAXTAP pruning),
// plus: all 32-bit indexing (offsets < 2^26) and explicit two-row
// interleaving in phase 2 for LDS latency overlap.

#define OUTS   224
#define BATCH  8
#define CHAN   3
#define HW     512
#define CUTN   32
#define NPLANE (BATCH * CHAN)   // 24
#define YG     8                // output rows per block
#define NYG    (OUTS / YG)      // 28
#define BPH    4                // bins per half
#define CSTRIDE 516

__device__ __forceinline__ float inv_small(int n) {
    return n == 1 ? 1.0f : (n == 2 ? 0.5f : (n == 3 ? (1.0f / 3.0f) : 0.25f));
}

__device__ __forceinline__ void f4add(float4& a, const float4 b) {
    a.x += b.x; a.y += b.y; a.z += b.z; a.w += b.w;
}

__global__ __launch_bounds__(256)
void makecutouts_v11(const float* __restrict__ x,
                     const int* __restrict__ sizes,
                     const int* __restrict__ offy,
                     const int* __restrict__ offx,
                     float* __restrict__ out)
{
    __shared__ float buf[YG][CSTRIDE];   // 16,512 B
    __shared__ float invy_sh[YG];

    const int tid = threadIdx.x;
    int bid = blockIdx.x;
    const int yg    = bid % NYG;  bid /= NYG;
    const int plane = bid % NPLANE;
    const int cut   = bid / NPLANE;

    const int sz = __ldg(sizes + cut);
    const int oy = __ldg(offy + cut);
    const int ox = __ldg(offx + cut);

    const int ox_al = ox & ~3;
    const int shift = ox - ox_al;        // 0..3
    const int span  = shift + sz;        // <= 515
    const int y0 = yg * YG;

    if (tid < YG) {
        const int yy = y0 + tid;
        const int ny = ((yy + 1) * sz + (OUTS - 1)) / OUTS - (yy * sz) / OUTS;
        invy_sh[tid] = inv_small(ny);
    }

    // 32-bit base offset: plane*262144 + oy*512 + ox_al < 2^23
    const float* pbase = x + (plane * (HW * HW) + oy * HW + ox_al);

    const int lane = tid & 127;
    const int half = tid >> 7;
    const int rem  = span - lane * 4;
    const int col4 = lane * 4;
    const int yb   = y0 + half * BPH;

    const bool small = (sz <= 448);      // uniform per block

    // ================= Phase 1 =================
    if (small) {
        if (rem >= 4) {
            float4 last; int pe = -1000;
            #pragma unroll
            for (int j = 0; j < BPH; j++) {
                const int y  = yb + j;
                const int sy = (y * sz) / OUTS;
                const int ey = ((y + 1) * sz + (OUTS - 1)) / OUTS;
                const int ny = ey - sy;           // 1..3
                const float* rp = pbase + (sy * HW + col4);

                float4 acc, l;
                if (sy == pe - 1) { acc = last; l = last; }
                else              { l = __ldg((const float4*)rp); acc = l; }
                if (ny > 1) { l = __ldg((const float4*)(rp + HW));     f4add(acc, l); }
                if (ny > 2) { l = __ldg((const float4*)(rp + 2 * HW)); f4add(acc, l); }
                *(float4*)&buf[half * BPH + j][col4] = acc;
                last = l; pe = ey;
            }
        } else if (rem > 0) {
            #pragma unroll
            for (int j = 0; j < BPH; j++) {
                const int y  = yb + j;
                const int sy = (y * sz) / OUTS;
                const int ny = ((y + 1) * sz + (OUTS - 1)) / OUTS - sy;
                const float* rp = pbase + (sy * HW + col4);
                #pragma unroll
                for (int k = 0; k < 3; k++) {
                    if (k < rem) {
                        float s = __ldg(rp + k);
                        if (ny > 1) s += __ldg(rp + k + HW);
                        if (ny > 2) s += __ldg(rp + k + 2 * HW);
                        buf[half * BPH + j][col4 + k] = s;
                    }
                }
            }
        }
    } else {
        if (rem >= 4) {
            float4 last; int pe = -1000;
            #pragma unroll
            for (int j = 0; j < BPH; j++) {
                const int y  = yb + j;
                const int sy = (y * sz) / OUTS;
                const int ey = ((y + 1) * sz + (OUTS - 1)) / OUTS;
                const int ny = ey - sy;           // 1..4
                const float* rp = pbase + (sy * HW + col4);

                float4 acc, l;
                if (sy == pe - 1) { acc = last; l = last; }
                else              { l = __ldg((const float4*)rp); acc = l; }
                if (ny > 1) { l = __ldg((const float4*)(rp + HW));     f4add(acc, l); }
                if (ny > 2) { l = __ldg((const float4*)(rp + 2 * HW)); f4add(acc, l); }
                if (ny > 3) { l = __ldg((const float4*)(rp + 3 * HW)); f4add(acc, l); }
                *(float4*)&buf[half * BPH + j][col4] = acc;
                last = l; pe = ey;
            }
        } else if (rem > 0) {
            #pragma unroll
            for (int j = 0; j < BPH; j++) {
                const int y  = yb + j;
                const int sy = (y * sz) / OUTS;
                const int ny = ((y + 1) * sz + (OUTS - 1)) / OUTS - sy;
                const float* rp = pbase + (sy * HW + col4);
                #pragma unroll
                for (int k = 0; k < 3; k++) {
                    if (k < rem) {
                        float s = __ldg(rp + k);
                        if (ny > 1) s += __ldg(rp + k + HW);
                        if (ny > 2) s += __ldg(rp + k + 2 * HW);
                        if (ny > 3) s += __ldg(rp + k + 3 * HW);
                        buf[half * BPH + j][col4 + k] = s;
                    }
                }
            }
        }
        if (span > 512 && tid == 126) {   // cols 512..514 (rare)
            #pragma unroll 1
            for (int j = 0; j < YG; j++) {
                const int y  = y0 + j;
                const int sy = (y * sz) / OUTS;
                const int ny = ((y + 1) * sz + (OUTS - 1)) / OUTS - sy;
                #pragma unroll
                for (int c = 512; c < 515; c++) {
                    if (c < span) {
                        const float* q = pbase + (sy * HW + c);
                        float s = __ldg(q);
                        if (ny > 1) s += __ldg(q + HW);
                        if (ny > 2) s += __ldg(q + 2 * HW);
                        if (ny > 3) s += __ldg(q + 3 * HW);
                        buf[j][c] = s;
                    }
                }
            }
        }
    }

    __syncthreads();

    // ================= Phase 2: two rows interleaved =================
    if (tid < OUTS) {
        const int sx = (tid * sz) / OUTS;
        const int ex = ((tid + 1) * sz + (OUTS - 1)) / OUTS;
        const int nx = ex - sx;              // 1..4 (<=3 when small)
        const float invx = inv_small(nx);
        const int off = shift + sx;

        int oidx = ((cut * NPLANE + plane) * OUTS + y0) * OUTS + tid;

        if (small) {
            const bool t2 = nx > 1, t3 = nx > 2;
            #pragma unroll
            for (int i = 0; i < YG; i += 2) {
                const float* p0 = &buf[i][off];
                const float* p1 = &buf[i + 1][off];
                float s0 = p0[0], s1 = p1[0];
                float a0, a1, b0, b1;
                if (t2) { a0 = p0[1]; a1 = p1[1]; }
                if (t3) { b0 = p0[2]; b1 = p1[2]; }
                if (t2) { s0 += a0; s1 += a1; }
                if (t3) { s0 += b0; s1 += b1; }
                out[oidx]        = s0 * (invx * invy_sh[i]);
                out[oidx + OUTS] = s1 * (invx * invy_sh[i + 1]);
                oidx += 2 * OUTS;
            }
        } else {
            const bool t2 = nx > 1, t3 = nx > 2, t4 = nx > 3;
            #pragma unroll
            for (int i = 0; i < YG; i += 2) {
                const float* p0 = &buf[i][off];
                const float* p1 = &buf[i + 1][off];
                float s0 = p0[0], s1 = p1[0];
                float a0, a1, b0, b1, c0, c1;
                if (t2) { a0 = p0[1]; a1 = p1[1]; }
                if (t3) { b0 = p0[2]; b1 = p1[2]; }
                if (t4) { c0 = p0[3]; c1 = p1[3]; }
                if (t2) { s0 += a0; s1 += a1; }
                if (t3) { s0 += b0; s1 += b1; }
                if (t4) { s0 += c0; s1 += c1; }
                out[oidx]        = s0 * (invx * invy_sh[i]);
                out[oidx + OUTS] = s1 * (invx * invy_sh[i + 1]);
                oidx += 2 * OUTS;
            }
        }
    }
}

extern "C" void kernel_launch(void* const* d_in, const int* in_sizes, int n_in,
                              void* d_out, int out_size)
{
    const float* x     = (const float*)d_in[0];
    const int*   sizes = (const int*)d_in[1];
    const int*   oy    = (const int*)d_in[2];
    const int*   ox    = (const int*)d_in[3];
    float* out = (float*)d_out;

    const int blocks = CUTN * NPLANE * NYG;   // 21504
    makecutouts_v11<<<blocks, 256>>>(x, sizes, oy, ox, out);
}